// round 11
// baseline (speedup 1.0000x reference)
#include <cuda_runtime.h>
#include <cuda_bf16.h>

#define NN 30000
#define MM 16
#define KK 8
#define DDIM 32
#define DREP 256
#define NFEAT 1024
#define NCLASS 16

typedef unsigned long long ull;

// Scratch (device globals: allowed, no runtime allocation)
__device__ float g_h[NN * DREP];                 // gemm output
__device__ float g_xn_a[(NN + 1) * DREP];        // normalized table A (+pad)
__device__ float g_xn_b[(NN + 1) * DREP];        // normalized table B (+pad)
__device__ float g_fcwT[KK * DDIM * DDIM];       // fc_w transposed [k][i][o]

// ---------------------------------------------------------------------------
// Packed f32x2 helpers (Blackwell FFMA2 family: 2x fp32 throughput)
// ---------------------------------------------------------------------------
__device__ __forceinline__ ull pack_dup(float x) {
    ull d;
    asm("mov.b64 %0, {%1, %1};" : "=l"(d) : "r"(__float_as_uint(x)));
    return d;
}
__device__ __forceinline__ float2 unpk(ull d) {
    unsigned lo, hi;
    asm("mov.b64 {%0, %1}, %2;" : "=r"(lo), "=r"(hi) : "l"(d));
    return make_float2(__uint_as_float(lo), __uint_as_float(hi));
}
__device__ __forceinline__ ull pack2(float x, float y) {
    ull d;
    asm("mov.b64 %0, {%1, %2};" : "=l"(d)
        : "r"(__float_as_uint(x)), "r"(__float_as_uint(y)));
    return d;
}
__device__ __forceinline__ ull fma2(ull a, ull b, ull c) {
    ull d;
    asm("fma.rn.f32x2 %0, %1, %2, %3;" : "=l"(d) : "l"(a), "l"(b), "l"(c));
    return d;
}
__device__ __forceinline__ ull mul2(ull a, ull b) {
    ull d;
    asm("mul.rn.f32x2 %0, %1, %2;" : "=l"(d) : "l"(a), "l"(b));
    return d;
}
__device__ __forceinline__ ull add2(ull a, ull b) {
    ull d;
    asm("add.rn.f32x2 %0, %1, %2;" : "=l"(d) : "l"(a), "l"(b));
    return d;
}

// ---------------------------------------------------------------------------
// PCA GEMM: C = relu(A[NN,1024] @ B[1024,256] + bias), fp32 via FFMA2
// BM=128, BN=128, BK=16, 256 threads, 8x8 micro-tile; double-buffered smem.
// ---------------------------------------------------------------------------
#define GBM 128
#define GBN 128
#define GBK 16
#define GNT (NFEAT / GBK)   // 64 k-tiles

__global__ __launch_bounds__(256) void pca_gemm_kernel(
    const float* __restrict__ A, const float* __restrict__ B,
    const float* __restrict__ bias, float* __restrict__ C)
{
    __shared__ alignas(16) float As[2][GBK][132];   // transposed, padded
    __shared__ alignas(16) float Bs[2][GBK][GBN];

    const int tid = threadIdx.x;
    const int rowBase = blockIdx.x * GBM;
    const int colBase = blockIdx.y * GBN;
    const int ty = tid >> 4;
    const int tx = tid & 15;

    const int ar = tid >> 2;
    const int ac = (tid & 3) << 2;
    const int br = tid >> 5;
    const int bc = (tid & 31) << 2;

    ull acc2[4][8];
#pragma unroll
    for (int i = 0; i < 4; i++)
#pragma unroll
        for (int j = 0; j < 8; j++) acc2[i][j] = 0ull;

    float4 pa0, pa1, pb0, pb1;

    {
        int r0 = rowBase + ar, r1 = rowBase + ar + 64;
        const float* ab = A + ac;
        pa0 = (r0 < NN) ? *(const float4*)(ab + (size_t)r0 * NFEAT)
                        : make_float4(0.f, 0.f, 0.f, 0.f);
        pa1 = (r1 < NN) ? *(const float4*)(ab + (size_t)r1 * NFEAT)
                        : make_float4(0.f, 0.f, 0.f, 0.f);
        const float* bb = B + colBase + bc;
        pb0 = *(const float4*)(bb + (size_t)br * DREP);
        pb1 = *(const float4*)(bb + (size_t)(br + 8) * DREP);
    }
    {
        As[0][ac + 0][ar] = pa0.x; As[0][ac + 1][ar] = pa0.y;
        As[0][ac + 2][ar] = pa0.z; As[0][ac + 3][ar] = pa0.w;
        As[0][ac + 0][ar + 64] = pa1.x; As[0][ac + 1][ar + 64] = pa1.y;
        As[0][ac + 2][ar + 64] = pa1.z; As[0][ac + 3][ar + 64] = pa1.w;
        *(float4*)&Bs[0][br][bc] = pb0;
        *(float4*)&Bs[0][br + 8][bc] = pb1;
    }
    __syncthreads();

    for (int t = 0; t < GNT; t++) {
        const int buf = t & 1;
        if (t + 1 < GNT) {
            int koff = (t + 1) * GBK;
            int r0 = rowBase + ar, r1 = rowBase + ar + 64;
            const float* ab = A + koff + ac;
            pa0 = (r0 < NN) ? *(const float4*)(ab + (size_t)r0 * NFEAT)
                            : make_float4(0.f, 0.f, 0.f, 0.f);
            pa1 = (r1 < NN) ? *(const float4*)(ab + (size_t)r1 * NFEAT)
                            : make_float4(0.f, 0.f, 0.f, 0.f);
            const float* bb = B + (size_t)koff * DREP + colBase + bc;
            pb0 = *(const float4*)(bb + (size_t)br * DREP);
            pb1 = *(const float4*)(bb + (size_t)(br + 8) * DREP);
        }

#pragma unroll
        for (int kk = 0; kk < GBK; kk++) {
            ulonglong2 aa0 = *(const ulonglong2*)&As[buf][kk][ty * 8];
            ulonglong2 aa1 = *(const ulonglong2*)&As[buf][kk][ty * 8 + 4];
            float4 b0 = *(const float4*)&Bs[buf][kk][tx * 4];
            float4 b1 = *(const float4*)&Bs[buf][kk][64 + tx * 4];
            ull av[4] = {aa0.x, aa0.y, aa1.x, aa1.y};
            ull bd[8] = {
                pack_dup(b0.x), pack_dup(b0.y), pack_dup(b0.z), pack_dup(b0.w),
                pack_dup(b1.x), pack_dup(b1.y), pack_dup(b1.z), pack_dup(b1.w)};
#pragma unroll
            for (int i = 0; i < 4; i++)
#pragma unroll
                for (int j = 0; j < 8; j++)
                    acc2[i][j] = fma2(av[i], bd[j], acc2[i][j]);
        }

        if (t + 1 < GNT) {
            int nb = (t + 1) & 1;
            As[nb][ac + 0][ar] = pa0.x; As[nb][ac + 1][ar] = pa0.y;
            As[nb][ac + 2][ar] = pa0.z; As[nb][ac + 3][ar] = pa0.w;
            As[nb][ac + 0][ar + 64] = pa1.x; As[nb][ac + 1][ar + 64] = pa1.y;
            As[nb][ac + 2][ar + 64] = pa1.z; As[nb][ac + 3][ar + 64] = pa1.w;
            *(float4*)&Bs[nb][br][bc] = pb0;
            *(float4*)&Bs[nb][br + 8][bc] = pb1;
            __syncthreads();
        }
    }

    float4 bi0 = *(const float4*)(bias + colBase + tx * 4);
    float4 bi1 = *(const float4*)(bias + colBase + 64 + tx * 4);
#pragma unroll
    for (int ip = 0; ip < 4; ip++) {
        int row0 = rowBase + ty * 8 + 2 * ip;
        float2 c[8];
#pragma unroll
        for (int j = 0; j < 8; j++) c[j] = unpk(acc2[ip][j]);
        if (row0 < NN) {
            float4 o0 = make_float4(fmaxf(c[0].x + bi0.x, 0.f), fmaxf(c[1].x + bi0.y, 0.f),
                                    fmaxf(c[2].x + bi0.z, 0.f), fmaxf(c[3].x + bi0.w, 0.f));
            float4 o1 = make_float4(fmaxf(c[4].x + bi1.x, 0.f), fmaxf(c[5].x + bi1.y, 0.f),
                                    fmaxf(c[6].x + bi1.z, 0.f), fmaxf(c[7].x + bi1.w, 0.f));
            *(float4*)(C + (size_t)row0 * DREP + colBase + tx * 4) = o0;
            *(float4*)(C + (size_t)row0 * DREP + colBase + 64 + tx * 4) = o1;
        }
        if (row0 + 1 < NN) {
            float4 o0 = make_float4(fmaxf(c[0].y + bi0.x, 0.f), fmaxf(c[1].y + bi0.y, 0.f),
                                    fmaxf(c[2].y + bi0.z, 0.f), fmaxf(c[3].y + bi0.w, 0.f));
            float4 o1 = make_float4(fmaxf(c[4].y + bi1.x, 0.f), fmaxf(c[5].y + bi1.y, 0.f),
                                    fmaxf(c[6].y + bi1.z, 0.f), fmaxf(c[7].y + bi1.w, 0.f));
            *(float4*)(C + (size_t)(row0 + 1) * DREP + colBase + tx * 4) = o0;
            *(float4*)(C + (size_t)(row0 + 1) * DREP + colBase + 64 + tx * 4) = o1;
        }
    }
}

// ---------------------------------------------------------------------------
// Transpose fc_w [k][o][i] -> g_fcwT [k][i][o] (one-time, tiny)
// ---------------------------------------------------------------------------
__global__ __launch_bounds__(256) void fcw_transpose_kernel(
    const float* __restrict__ fc_w)
{
    int g = blockIdx.x * 256 + threadIdx.x;   // 0..8191
    int k = g >> 10;
    int r = g & 1023;
    int o = r >> 5;
    int i = r & 31;
    g_fcwT[k * 1024 + i * 32 + o] = fc_w[g];
}

// ---------------------------------------------------------------------------
// Prep layer 0: per-capsule l2norm -> fc (coalesced transposed weights)
// + relu -> l2norm
// ---------------------------------------------------------------------------
__global__ __launch_bounds__(256) void prep0_kernel(
    const float* __restrict__ fc_b)
{
    int n = blockIdx.x;
    int t = threadIdx.x;
    int k = t >> 5;
    int o = t & 31;
    if (n == NN) { g_xn_a[(size_t)NN * DREP + t] = 0.f; return; }

    __shared__ float sx[DREP];
    float xv = g_h[(size_t)n * DREP + t];
    float ss = xv * xv;
#pragma unroll
    for (int off = 16; off >= 1; off >>= 1)
        ss += __shfl_xor_sync(0xffffffffu, ss, off);
    float xn = xv / fmaxf(sqrtf(ss), 1e-12f);
    sx[t] = xn;
    __syncthreads();

    float y = fc_b[k * DDIM + o];
    const float* wT = g_fcwT + k * DDIM * DDIM + o;
    const float* xk = &sx[k * DDIM];
#pragma unroll
    for (int i = 0; i < DDIM; i++)
        y = fmaf(xk[i], wT[i * DDIM], y);
    y = fmaxf(y, 0.f);

    float ss2 = y * y;
#pragma unroll
    for (int off = 16; off >= 1; off >>= 1)
        ss2 += __shfl_xor_sync(0xffffffffu, ss2, off);
    g_xn_a[(size_t)n * DREP + t] = y / fmaxf(sqrtf(ss2), 1e-12f);
}

// ---------------------------------------------------------------------------
// Routing v2: 128 threads per node (2 nodes per 256-block).
// Thread tt (0..127): capsule g = tt>>4, dd-PAIR li = tt&15; all per-dd math
// packed in f32x2 (z[m], u as ull). 16-lane multi-reduce (4 select-steps)
// leaves p[m=li] per lane. Iteration 0 hoisted (uniform softmax).
// s1: 4-shfl reduce; s2: 1 capsule-pair shfl + smem (4 LDS), double-buffered.
// mode 0: relu + per-capsule l2norm -> dst (grid NN/2+1, pad block)
// mode 1: final -> h to dst + fused MLP + log_softmax (grid NN/2)
// ---------------------------------------------------------------------------
__global__ __launch_bounds__(256) void routing_kernel(
    const int* __restrict__ nbrs, const float* __restrict__ raw_param,
    const int* __restrict__ routit_p,
    const float* __restrict__ src_xn, float* __restrict__ dst,
    int mode,
    const float* __restrict__ mlp_w, const float* __restrict__ mlp_b,
    float* __restrict__ out_logp)
{
    const int t = threadIdx.x;
    const int half = t >> 7;          // node within block
    const int tt = t & 127;
    const int g = tt >> 4;            // capsule 0..7
    const int li = tt & 15;           // dd-pair index
    const int wi = tt >> 5;           // warp-in-node 0..3
    const int lane = t & 31;
    const int n = blockIdx.x * 2 + half;

    __shared__ int snbr[2][MM];
    __shared__ float sw2[2][2][4][16];   // [parity][half][warp][m]
    __shared__ float su[2][DREP];
    __shared__ float slog[2][NCLASS];

    if (mode == 0) {
        if (n > NN) return;
        if (n == NN) {   // pad row: 128 threads write 256 zeros
            *(float2*)&dst[(size_t)NN * DREP + tt * 2] = make_float2(0.f, 0.f);
            return;
        }
    }

    if (tt < MM) snbr[half][tt] = nbrs[(size_t)n * MM + tt];
    __syncthreads();

    const int off = g * DDIM + li * 2;
    ull z[MM];
#pragma unroll
    for (int m = 0; m < MM; m++) {
        int nb = snbr[half][m];
        z[m] = *(const ull*)&src_xn[(size_t)nb * DREP + off];
    }
    ull u = *(const ull*)&src_xn[(size_t)n * DREP + off];

    float param = 1.f / (1.f + __expf(-raw_param[0]));
    float q = 1.f - param;
    int nit = *routit_p;

    // --- iteration 0 (p==0 -> uniform softmaxes 1/16, 1/8) ---
    {
        ull zs = z[0];
#pragma unroll
        for (int m = 1; m < MM; m++) zs = add2(zs, z[m]);
        float w0 = param * (1.f / 16.f) + q * (1.f / 8.f);
        u = fma2(zs, pack_dup(w0), u);
    }
    ull u_n = u;
    if (nit > 1) {
        float2 uf = unpk(u);
        float ss = fmaf(uf.x, uf.x, uf.y * uf.y);
#pragma unroll
        for (int o2 = 8; o2 >= 1; o2 >>= 1)
            ss += __shfl_xor_sync(0xffffffffu, ss, o2);
        float inv = __fdividef(1.f, fmaxf(sqrtf(ss), 1e-12f));
        u_n = mul2(u, pack_dup(inv));
    }

    for (int it = 1; it < nit; it++) {
        // p[m] = <z[m], u_n> : packed mul, horizontal add, 16-lane multi-reduce
        float vh[MM];
#pragma unroll
        for (int m = 0; m < MM; m++) {
            float2 f = unpk(mul2(z[m], u_n));
            vh[m] = f.x + f.y;
        }
        {
            bool hb = li & 1;
#pragma unroll
            for (int j = 0; j < 8; j++) {
                float keep = hb ? vh[2 * j + 1] : vh[2 * j];
                float send = hb ? vh[2 * j] : vh[2 * j + 1];
                vh[j] = keep + __shfl_xor_sync(0xffffffffu, send, 1);
            }
        }
        {
            bool hb = (li >> 1) & 1;
#pragma unroll
            for (int j = 0; j < 4; j++) {
                float keep = hb ? vh[2 * j + 1] : vh[2 * j];
                float send = hb ? vh[2 * j] : vh[2 * j + 1];
                vh[j] = keep + __shfl_xor_sync(0xffffffffu, send, 2);
            }
        }
        {
            bool hb = (li >> 2) & 1;
#pragma unroll
            for (int j = 0; j < 2; j++) {
                float keep = hb ? vh[2 * j + 1] : vh[2 * j];
                float send = hb ? vh[2 * j] : vh[2 * j + 1];
                vh[j] = keep + __shfl_xor_sync(0xffffffffu, send, 4);
            }
        }
        {
            bool hb = (li >> 3) & 1;
            float keep = hb ? vh[1] : vh[0];
            float send = hb ? vh[0] : vh[1];
            vh[0] = keep + __shfl_xor_sync(0xffffffffu, send, 8);
        }
        float e = __expf(vh[0]);       // lane li holds e[g][m=li]; |p|<=1

        // s1 = sum_m e[g][m] (within 16-lane group)
        float s1 = e;
        s1 += __shfl_xor_sync(0xffffffffu, s1, 1);
        s1 += __shfl_xor_sync(0xffffffffu, s1, 2);
        s1 += __shfl_xor_sync(0xffffffffu, s1, 4);
        s1 += __shfl_xor_sync(0xffffffffu, s1, 8);

        // s2 = sum_k e[k][m]: capsule-pair sum in-warp, then 4-warp smem
        float epair = e + __shfl_xor_sync(0xffffffffu, e, 16);
        int par = it & 1;
        if (lane < 16) sw2[par][half][wi][li] = epair;
        __syncthreads();
        float s2 = sw2[par][half][0][li] + sw2[par][half][1][li] +
                   sw2[par][half][2][li] + sw2[par][half][3][li];

        // w = e*(param/s1 + q/s2) = e*(param*s2 + q*s1)/(s1*s2)
        float num = fmaf(param, s2, q * s1);
        float w = e * __fdividef(num, s1 * s2);

        ull unew = u;
#pragma unroll
        for (int m = 0; m < MM; m++) {
            float wm = __shfl_sync(0xffffffffu, w, m, 16);
            unew = fma2(z[m], pack_dup(wm), unew);
        }
        u = unew;

        if (it < nit - 1) {
            float2 uf = unpk(u);
            float ss = fmaf(uf.x, uf.x, uf.y * uf.y);
#pragma unroll
            for (int o2 = 8; o2 >= 1; o2 >>= 1)
                ss += __shfl_xor_sync(0xffffffffu, ss, o2);
            float inv = __fdividef(1.f, fmaxf(sqrtf(ss), 1e-12f));
            u_n = mul2(u, pack_dup(inv));
        }
        // no trailing barrier: sw2 double-buffered by iteration parity
    }

    if (mode == 0) {
        float2 uf = unpk(u);
        float vx = fmaxf(uf.x, 0.f), vy = fmaxf(uf.y, 0.f);
        float ss = fmaf(vx, vx, vy * vy);
#pragma unroll
        for (int o2 = 8; o2 >= 1; o2 >>= 1)
            ss += __shfl_xor_sync(0xffffffffu, ss, o2);
        float inv = __fdividef(1.f, fmaxf(sqrtf(ss), 1e-12f));
        *(float2*)&dst[(size_t)n * DREP + off] = make_float2(vx * inv, vy * inv);
    } else {
        float2 uf = unpk(u);
        *(float2*)&dst[(size_t)n * DREP + off] = uf;
        *(float2*)&su[half][off] = uf;
        __syncthreads();
        // warp wi computes classes wi*4 .. wi*4+3 for its node
        float acc[4] = {0.f, 0.f, 0.f, 0.f};
#pragma unroll
        for (int j = 0; j < 8; j++) {
            float hv = su[half][lane + 32 * j];
#pragma unroll
            for (int c4 = 0; c4 < 4; c4++)
                acc[c4] = fmaf(hv,
                    __ldg(&mlp_w[(size_t)(wi * 4 + c4) * DREP + lane + 32 * j]),
                    acc[c4]);
        }
#pragma unroll
        for (int c4 = 0; c4 < 4; c4++) {
            float a = acc[c4];
#pragma unroll
            for (int o2 = 16; o2 >= 1; o2 >>= 1)
                a += __shfl_xor_sync(0xffffffffu, a, o2);
            if (lane == 0)
                slog[half][wi * 4 + c4] = a + __ldg(&mlp_b[wi * 4 + c4]);
        }
        __syncthreads();
        if (tt < 16) {    // lanes 0..15 of warp 0 (half0) / warp 4 (half1)
            float xv = slog[half][tt];
            float mx = xv;
#pragma unroll
            for (int o2 = 8; o2 >= 1; o2 >>= 1)
                mx = fmaxf(mx, __shfl_xor_sync(0xffffu, mx, o2));
            float ex = __expf(xv - mx);
            float s = ex;
#pragma unroll
            for (int o2 = 8; o2 >= 1; o2 >>= 1)
                s += __shfl_xor_sync(0xffffu, s, o2);
            out_logp[(size_t)n * NCLASS + tt] = xv - mx - __logf(s);
        }
    }
}

// ---------------------------------------------------------------------------
// Launch
// ---------------------------------------------------------------------------
extern "C" void kernel_launch(void* const* d_in, const int* in_sizes, int n_in,
                              void* d_out, int out_size)
{
    const float* x        = (const float*)d_in[0];
    const int*   nbrs     = (const int*)d_in[1];
    const float* pca_w    = (const float*)d_in[2];
    const float* pca_b    = (const float*)d_in[3];
    const float* rawp     = (const float*)d_in[4];
    const float* fc_w     = (const float*)d_in[5];
    const float* fc_b     = (const float*)d_in[6];
    const float* mlp_w    = (const float*)d_in[7];
    const float* mlp_b    = (const float*)d_in[8];
    const int*   routit_p = (const int*)d_in[9];

    float* out = (float*)d_out;
    float* out_logp = out;                       // [NN, 16]
    float* out_h = out + (size_t)NN * NCLASS;    // [NN, 256]

    float *h_buf, *xa, *xb;
    cudaGetSymbolAddress((void**)&h_buf, g_h);
    cudaGetSymbolAddress((void**)&xa, g_xn_a);
    cudaGetSymbolAddress((void**)&xb, g_xn_b);
    (void)in_sizes; (void)n_in; (void)out_size;

    // 0. One-time fc weight transpose (coalesces prep0's gather)
    fcw_transpose_kernel<<<KK * DDIM * DDIM / 256, 256>>>(fc_w);

    // 1. PCA projection + relu -> g_h
    dim3 ggrid((NN + GBM - 1) / GBM, DREP / GBN);
    pca_gemm_kernel<<<ggrid, 256>>>(x, pca_w, pca_b, h_buf);

    // 2. Layer-0 prep: capsule norm + fc + relu + norm -> xa (+ pad)
    prep0_kernel<<<NN + 1, 256>>>(fc_b);

    // 3. Routing layers: 2 nodes per block
    routing_kernel<<<NN / 2 + 1, 256>>>(nbrs, rawp, routit_p, xa, xb, 0,
                                        mlp_w, mlp_b, out_logp);
    routing_kernel<<<NN / 2 + 1, 256>>>(nbrs, rawp, routit_p, xb, xa, 0,
                                        mlp_w, mlp_b, out_logp);
    // 4. Final layer: embedding + fused MLP head
    routing_kernel<<<NN / 2, 256>>>(nbrs, rawp, routit_p, xa, out_h, 1,
                                    mlp_w, mlp_b, out_logp);
}